// round 15
// baseline (speedup 1.0000x reference)
#include <cuda_runtime.h>
#include <cuda_fp16.h>
#include <math.h>

#define XD 128
#define NDEPTH 222
#define MPAD 160
// max_extent = sqrt(3*(64^2)) * 1.5
static constexpr double MAX_EXTENT_D = 166.27687752661222232;
static constexpr double DT_D         = 2.0 * MAX_EXTENT_D / (NDEPTH - 1);
static constexpr double SCALE_D      = 2.0 * MAX_EXTENT_D / NDEPTH;

// fp16 copy of the volume (scratch; rebuilt every launch). Row = 256 B.
__device__ uint4 g_volh[XD * XD * XD / 8];

__global__ void __launch_bounds__(256)
convert_kernel(const float* __restrict__ vol) {
    const int i = blockIdx.x * 256 + threadIdx.x;   // one uint4 (8 halves) per thread
    const float4 v0 = __ldg((const float4*)vol + 2 * i);
    const float4 v1 = __ldg((const float4*)vol + 2 * i + 1);
    uint4 q;
    __half2 a = __floats2half2_rn(v0.x, v0.y);
    __half2 b = __floats2half2_rn(v0.z, v0.w);
    __half2 c = __floats2half2_rn(v1.x, v1.y);
    __half2 d = __floats2half2_rn(v1.z, v1.w);
    q.x = *(const unsigned*)&a;
    q.y = *(const unsigned*)&b;
    q.z = *(const unsigned*)&c;
    q.w = *(const unsigned*)&d;
    g_volh[i] = q;
}

__device__ __forceinline__ void slab_axis(float r, float b, float& tlo, float& thi, bool& empty) {
    if (fabsf(r) > 1e-12f) {
        float inv = __frcp_rn(r);
        float ta = (-1.0f - b) * inv;
        float tb = (128.0f - b) * inv;
        tlo = fmaxf(tlo, fminf(ta, tb));
        thi = fminf(thi, fmaxf(ta, tb));
    } else if (b <= -1.0f || b >= 128.0f) {
        empty = true;
    }
}

__device__ __forceinline__ __half2 h2u(unsigned u) { return *(const __half2*)&u; }

// Two steps' contribution (4 taps per lane-element) accumulated in fp16,
// upgraded to f32 once per pair.
__device__ __forceinline__ void pair_acc(float* S,
                                         unsigned w0A, unsigned w0B,
                                         unsigned w1A, unsigned w1B,
                                         const uint4& a0, const uint4& b0,
                                         const uint4& a1, const uint4& b1) {
    #pragma unroll
    for (int i = 0; i < 4; ++i) {
        __half2 t = __hmul2(h2u(w0A), h2u((&a0.x)[i]));
        t = __hfma2(h2u(w0B), h2u((&b0.x)[i]), t);
        t = __hfma2(h2u(w1A), h2u((&a1.x)[i]), t);
        t = __hfma2(h2u(w1B), h2u((&b1.x)[i]), t);
        const float2 f = __half22float2(t);
        S[2 * i + 0] += f.x;
        S[2 * i + 1] += f.y;
    }
}

__global__ void __launch_bounds__(128, 7)
projector_kernel(const float* __restrict__ vol,
                 const float* __restrict__ vec,
                 float* __restrict__ out) {
    const int tid = threadIdx.x;
    const int j   = blockIdx.x;
    const int n   = blockIdx.y;

    const float* V = vec + n * 12;
    const float rx = __ldg(V + 0), ry = __ldg(V + 1), rz = __ldg(V + 2);
    const float dx = __ldg(V + 3), dy = __ldg(V + 4), dz = __ldg(V + 5);
    const float ux = __ldg(V + 6), uy = __ldg(V + 7), uz = __ldg(V + 8);
    const float vx = __ldg(V + 9), vy = __ldg(V + 10), vz = __ldg(V + 11);

    const float t0 = (float)(-MAX_EXTENT_D);
    const float dt = (float)DT_D;
    const float jc = (float)j - 63.5f;

    // Per-step metadata: uint4 { h2(w00,w01), h2(w10,w11), row index, 0 }.
    __shared__ uint4 Ms[MPAD];
    __shared__ float Red[4][136];   // padded reduce buffer

    const bool fast = (rz == 0.0f) & (uz == 0.0f) & (dz == 0.0f) &
                      (vx == 0.0f) & (vy == 0.0f) & (vz == 1.0f);

    if (fast) {
        const int w    = tid >> 5;
        const int lane = tid & 31;
        // lane < 16: row y0 of the pair; lane >= 16: row y1. z = 8*(lane&15)+0..7.
        const unsigned psel = (lane < 16) ? 0x1010u : 0x3232u;

        const float bx = fmaf(jc, ux, dx) + 63.5f;
        const float by = fmaf(jc, uy, dy) + 63.5f;

        float tlo = -3.0e38f, thi = 3.0e38f;
        bool empty = false;
        slab_axis(rx, bx, tlo, thi, empty);
        slab_axis(ry, by, tlo, thi, empty);

        int i0 = 0, cnt = 0;
        if (!empty && thi >= tlo) {
            i0 = max(0, (int)ceilf((tlo - t0) / dt) - 1);
            int i1 = min(NDEPTH - 1, (int)floorf((thi - t0) / dt) + 1);
            cnt = i1 - i0 + 1;
            if (cnt < 0) cnt = 0;
        }
        const int cntPad = (cnt + 15) & ~15;   // 4 warps x unroll-4

        // Metadata phase — reads only vol-independent data; runs under PDL overlap.
        for (int m = tid; m < cntPad; m += 128) {
            if (m < cnt) {
                const float t  = fmaf((float)(i0 + m), dt, t0);
                const float px = fmaf(t, rx, bx);
                const float py = fmaf(t, ry, by);
                const float x0f = floorf(px);
                const float y0f = floorf(py);
                const float fx = px - x0f;
                const float fy = py - y0f;
                const int x0 = (int)x0f;
                const int y0 = (int)y0f;
                const float wx0 = ((unsigned)x0       < (unsigned)XD) ? (1.0f - fx) : 0.0f;
                const float wx1 = ((unsigned)(x0 + 1) < (unsigned)XD) ? fx          : 0.0f;
                const float wy0 = ((unsigned)y0       < (unsigned)XD) ? (1.0f - fy) : 0.0f;
                const float wy1 = ((unsigned)(y0 + 1) < (unsigned)XD) ? fy          : 0.0f;

                int   bxc;  float X0, X1;
                if (x0 < 0)        { bxc = 0;   X0 = wx1; X1 = 0.0f; }
                else if (x0 > 126) { bxc = 126; X0 = 0.0f; X1 = wx0; }
                else               { bxc = x0;  X0 = wx0; X1 = wx1; }
                int   byc;  float Y0, Y1;
                if (y0 < 0)        { byc = 0;   Y0 = wy1; Y1 = 0.0f; }
                else if (y0 > 126) { byc = 126; Y0 = 0.0f; Y1 = wy0; }
                else               { byc = y0;  Y0 = wy0; Y1 = wy1; }

                const unsigned ridx = (unsigned)(bxc * XD + byc);
                __half2 hA = __floats2half2_rn(X0 * Y0, X0 * Y1);   // (w00, w01)
                __half2 hB = __floats2half2_rn(X1 * Y0, X1 * Y1);   // (w10, w11)
                uint4 M;
                M.x = *(const unsigned*)&hA;
                M.y = *(const unsigned*)&hB;
                M.z = ridx;
                M.w = 0;
                Ms[m] = M;
            } else {
                Ms[m] = make_uint4(0, 0, 0, 0);
            }
        }
        __syncthreads();

        // Wait for the convert kernel's writes to g_volh (PDL edge; no-op if
        // the kernel was launched without the programmatic attribute).
        cudaGridDependencySynchronize();

        // Mainloop: 4 steps/trip, stride 16 -> 8 x LDG.128 in flight per warp.
        const char* volb = (const char*)g_volh + (lane << 4);
        float S[8];
        #pragma unroll
        for (int i = 0; i < 8; ++i) S[i] = 0.0f;

        for (int m = 4 * w; m < cntPad; m += 16) {
            const uint4 M0 = Ms[m];
            const uint4 M1 = Ms[m + 1];
            const uint4 M2 = Ms[m + 2];
            const uint4 M3 = Ms[m + 3];
            const char* p0 = volb + ((size_t)M0.z << 8);
            const char* p1 = volb + ((size_t)M1.z << 8);
            const char* p2 = volb + ((size_t)M2.z << 8);
            const char* p3 = volb + ((size_t)M3.z << 8);
            const uint4 a0 = __ldg((const uint4*)(p0));
            const uint4 b0 = __ldg((const uint4*)(p0 + 32768));
            const uint4 a1 = __ldg((const uint4*)(p1));
            const uint4 b1 = __ldg((const uint4*)(p1 + 32768));
            const uint4 a2 = __ldg((const uint4*)(p2));
            const uint4 b2 = __ldg((const uint4*)(p2 + 32768));
            const uint4 a3 = __ldg((const uint4*)(p3));
            const uint4 b3 = __ldg((const uint4*)(p3 + 32768));
            pair_acc(S, __byte_perm(M0.x, 0, psel), __byte_perm(M0.y, 0, psel),
                        __byte_perm(M1.x, 0, psel), __byte_perm(M1.y, 0, psel),
                     a0, b0, a1, b1);
            pair_acc(S, __byte_perm(M2.x, 0, psel), __byte_perm(M2.y, 0, psel),
                        __byte_perm(M3.x, 0, psel), __byte_perm(M3.y, 0, psel),
                     a2, b2, a3, b3);
        }

        #pragma unroll
        for (int i = 0; i < 8; ++i)
            S[i] += __shfl_xor_sync(0xffffffffu, S[i], 16);
        if (lane < 16) {
            #pragma unroll
            for (int i = 0; i < 8; ++i)
                Red[w][(lane << 3) + i] = S[i];
        }
        __syncthreads();

        const float acc = Red[0][tid] + Red[1][tid] + Red[2][tid] + Red[3][tid];
        out[((n * XD) + j) * XD + tid] = acc * (float)SCALE_D;
    } else {
        // General path: per-pixel trilinear gather from the ORIGINAL fp32 volume.
        const int z = tid;
        const float kc = (float)z - 63.5f;
        const float bx = fmaf(kc, vx, fmaf(jc, ux, dx)) + 63.5f;
        const float by = fmaf(kc, vy, fmaf(jc, uy, dy)) + 63.5f;
        const float bz = fmaf(kc, vz, fmaf(jc, uz, dz)) + 63.5f;

        float tlo = -3.0e38f, thi = 3.0e38f;
        bool empty = false;
        slab_axis(rx, bx, tlo, thi, empty);
        slab_axis(ry, by, tlo, thi, empty);
        slab_axis(rz, bz, tlo, thi, empty);

        int i0 = 0, i1 = -1;
        if (!empty && thi >= tlo) {
            i0 = max(0, (int)ceilf((tlo - t0) / dt) - 1);
            i1 = min(NDEPTH - 1, (int)floorf((thi - t0) / dt) + 1);
        }

        float sum = 0.0f;
        for (int i = i0; i <= i1; ++i) {
            const float t  = fmaf((float)i, dt, t0);
            const float px = fmaf(t, rx, bx);
            const float py = fmaf(t, ry, by);
            const float pz = fmaf(t, rz, bz);

            const float x0f = floorf(px);
            const float y0f = floorf(py);
            const float z0f = floorf(pz);
            const float fx = px - x0f;
            const float fy = py - y0f;
            const float fz = pz - z0f;
            const int x0 = (int)x0f;
            const int y0 = (int)y0f;
            const int z0 = (int)z0f;

            const int a = x0 * (XD * XD) + y0 * XD + z0;

            const bool xv0 = ((unsigned)x0 < (unsigned)XD);
            const bool xv1 = ((unsigned)(x0 + 1) < (unsigned)XD);
            const bool yv0 = ((unsigned)y0 < (unsigned)XD);
            const bool yv1 = ((unsigned)(y0 + 1) < (unsigned)XD);
            const bool zv0 = ((unsigned)z0 < (unsigned)XD);
            const bool zv1 = ((unsigned)(z0 + 1) < (unsigned)XD);

            const float v000 = (xv0 & yv0 & zv0) ? __ldg(vol + a)                    : 0.0f;
            const float v001 = (xv0 & yv0 & zv1) ? __ldg(vol + a + 1)                : 0.0f;
            const float v010 = (xv0 & yv1 & zv0) ? __ldg(vol + a + XD)               : 0.0f;
            const float v011 = (xv0 & yv1 & zv1) ? __ldg(vol + a + XD + 1)           : 0.0f;
            const float v100 = (xv1 & yv0 & zv0) ? __ldg(vol + a + XD * XD)          : 0.0f;
            const float v101 = (xv1 & yv0 & zv1) ? __ldg(vol + a + XD * XD + 1)      : 0.0f;
            const float v110 = (xv1 & yv1 & zv0) ? __ldg(vol + a + XD * XD + XD)     : 0.0f;
            const float v111 = (xv1 & yv1 & zv1) ? __ldg(vol + a + XD * XD + XD + 1) : 0.0f;

            const float c00 = fmaf(fz, v001 - v000, v000);
            const float c01 = fmaf(fz, v011 - v010, v010);
            const float c10 = fmaf(fz, v101 - v100, v100);
            const float c11 = fmaf(fz, v111 - v110, v110);
            const float c0  = fmaf(fy, c01 - c00, c00);
            const float c1  = fmaf(fy, c11 - c10, c10);
            sum += fmaf(fx, c1 - c0, c0);
        }
        out[((n * XD) + j) * XD + z] = sum * (float)SCALE_D;
    }
}

extern "C" void kernel_launch(void* const* d_in, const int* in_sizes, int n_in,
                              void* d_out, int out_size) {
    const float* vol = (const float*)d_in[0];
    const float* vec = (const float*)d_in[1];
    float* out = (float*)d_out;

    const int N = in_sizes[1] / 12;
    convert_kernel<<<XD * XD * XD / 8 / 256, 256>>>(vol);

    // Launch projector with programmatic dependent launch so its metadata phase
    // overlaps the convert kernel; it grid-dep-syncs before reading g_volh.
    cudaLaunchConfig_t cfg = {};
    cfg.gridDim  = dim3(XD, (unsigned)N);
    cfg.blockDim = dim3(128);
    cfg.dynamicSmemBytes = 0;
    cfg.stream = 0;
    cudaLaunchAttribute attrs[1];
    attrs[0].id = cudaLaunchAttributeProgrammaticStreamSerialization;
    attrs[0].val.programmaticStreamSerializationAllowed = 1;
    cfg.attrs = attrs;
    cfg.numAttrs = 1;
    cudaError_t e = cudaLaunchKernelEx(&cfg, projector_kernel, vol, vec, out);
    if (e != cudaSuccess) {
        // Fallback: plain launch (grid-dep-sync degenerates to a no-op).
        dim3 grid(XD, N);
        dim3 block(128);
        projector_kernel<<<grid, block>>>(vol, vec, out);
    }
}

// round 16
// speedup vs baseline: 1.5063x; 1.5063x over previous
#include <cuda_runtime.h>
#include <cuda_fp16.h>
#include <math.h>

#define XD 128
#define NDEPTH 222
#define MPAD 160
// max_extent = sqrt(3*(64^2)) * 1.5
static constexpr double MAX_EXTENT_D = 166.27687752661222232;
static constexpr double DT_D         = 2.0 * MAX_EXTENT_D / (NDEPTH - 1);
static constexpr double SCALE_D      = 2.0 * MAX_EXTENT_D / NDEPTH;

// fp16 copy of the volume (scratch; rebuilt every launch). Row = 256 B.
__device__ uint4 g_volh[XD * XD * XD / 8];

__global__ void __launch_bounds__(256)
convert_kernel(const float* __restrict__ vol) {
    const int i = blockIdx.x * 256 + threadIdx.x;   // one uint4 (8 halves) per thread
    const float4 v0 = __ldg((const float4*)vol + 2 * i);
    const float4 v1 = __ldg((const float4*)vol + 2 * i + 1);
    uint4 q;
    __half2 a = __floats2half2_rn(v0.x, v0.y);
    __half2 b = __floats2half2_rn(v0.z, v0.w);
    __half2 c = __floats2half2_rn(v1.x, v1.y);
    __half2 d = __floats2half2_rn(v1.z, v1.w);
    q.x = *(const unsigned*)&a;
    q.y = *(const unsigned*)&b;
    q.z = *(const unsigned*)&c;
    q.w = *(const unsigned*)&d;
    g_volh[i] = q;
}

__device__ __forceinline__ void slab_axis(float r, float b, float& tlo, float& thi, bool& empty) {
    if (fabsf(r) > 1e-12f) {
        float inv = __frcp_rn(r);
        float ta = (-1.0f - b) * inv;
        float tb = (128.0f - b) * inv;
        tlo = fmaxf(tlo, fminf(ta, tb));
        thi = fminf(thi, fmaxf(ta, tb));
    } else if (b <= -1.0f || b >= 128.0f) {
        empty = true;
    }
}

__device__ __forceinline__ __half2 h2u(unsigned u) { return *(const __half2*)&u; }

// Two steps' contribution (4 taps per lane-element) accumulated in fp16,
// upgraded to f32 once per pair. Measured aggregate rel_err ~4.2e-4.
__device__ __forceinline__ void pair_acc(float* S,
                                         unsigned w0A, unsigned w0B,
                                         unsigned w1A, unsigned w1B,
                                         const uint4& a0, const uint4& b0,
                                         const uint4& a1, const uint4& b1) {
    #pragma unroll
    for (int i = 0; i < 4; ++i) {
        __half2 t = __hmul2(h2u(w0A), h2u((&a0.x)[i]));
        t = __hfma2(h2u(w0B), h2u((&b0.x)[i]), t);
        t = __hfma2(h2u(w1A), h2u((&a1.x)[i]), t);
        t = __hfma2(h2u(w1B), h2u((&b1.x)[i]), t);
        const float2 f = __half22float2(t);
        S[2 * i + 0] += f.x;
        S[2 * i + 1] += f.y;
    }
}

__global__ void __launch_bounds__(128, 7)
projector_kernel(const float* __restrict__ vol,
                 const float* __restrict__ vec,
                 float* __restrict__ out) {
    const int tid = threadIdx.x;
    const int j   = blockIdx.x;
    const int n   = blockIdx.y;

    const float* V = vec + n * 12;
    const float rx = __ldg(V + 0), ry = __ldg(V + 1), rz = __ldg(V + 2);
    const float dx = __ldg(V + 3), dy = __ldg(V + 4), dz = __ldg(V + 5);
    const float ux = __ldg(V + 6), uy = __ldg(V + 7), uz = __ldg(V + 8);
    const float vx = __ldg(V + 9), vy = __ldg(V + 10), vz = __ldg(V + 11);

    const float t0 = (float)(-MAX_EXTENT_D);
    const float dt = (float)DT_D;
    const float jc = (float)j - 63.5f;

    // Per-step metadata: uint4 { h2(w00,w01), h2(w10,w11), row index, 0 }.
    __shared__ uint4 Ms[MPAD];
    __shared__ float Red[4][136];   // padded reduce buffer

    const bool fast = (rz == 0.0f) & (uz == 0.0f) & (dz == 0.0f) &
                      (vx == 0.0f) & (vy == 0.0f) & (vz == 1.0f);

    if (fast) {
        const int w    = tid >> 5;
        const int lane = tid & 31;
        // lane < 16: row y0 of the pair; lane >= 16: row y1. z = 8*(lane&15)+0..7.
        const unsigned psel = (lane < 16) ? 0x1010u : 0x3232u;

        const float bx = fmaf(jc, ux, dx) + 63.5f;
        const float by = fmaf(jc, uy, dy) + 63.5f;

        float tlo = -3.0e38f, thi = 3.0e38f;
        bool empty = false;
        slab_axis(rx, bx, tlo, thi, empty);
        slab_axis(ry, by, tlo, thi, empty);

        int i0 = 0, cnt = 0;
        if (!empty && thi >= tlo) {
            i0 = max(0, (int)ceilf((tlo - t0) / dt) - 1);
            int i1 = min(NDEPTH - 1, (int)floorf((thi - t0) / dt) + 1);
            cnt = i1 - i0 + 1;
            if (cnt < 0) cnt = 0;
        }
        const int cntPad = (cnt + 15) & ~15;   // 4 warps x unroll-4

        // Metadata phase.
        for (int m = tid; m < cntPad; m += 128) {
            if (m < cnt) {
                const float t  = fmaf((float)(i0 + m), dt, t0);
                const float px = fmaf(t, rx, bx);
                const float py = fmaf(t, ry, by);
                const float x0f = floorf(px);
                const float y0f = floorf(py);
                const float fx = px - x0f;
                const float fy = py - y0f;
                const int x0 = (int)x0f;
                const int y0 = (int)y0f;
                const float wx0 = ((unsigned)x0       < (unsigned)XD) ? (1.0f - fx) : 0.0f;
                const float wx1 = ((unsigned)(x0 + 1) < (unsigned)XD) ? fx          : 0.0f;
                const float wy0 = ((unsigned)y0       < (unsigned)XD) ? (1.0f - fy) : 0.0f;
                const float wy1 = ((unsigned)(y0 + 1) < (unsigned)XD) ? fy          : 0.0f;

                // Base-shift per axis: base cell in [0,126]; shifted-out cells have
                // zero weight; valid cells keep their exact slot/address.
                int   bxc;  float X0, X1;
                if (x0 < 0)        { bxc = 0;   X0 = wx1; X1 = 0.0f; }
                else if (x0 > 126) { bxc = 126; X0 = 0.0f; X1 = wx0; }
                else               { bxc = x0;  X0 = wx0; X1 = wx1; }
                int   byc;  float Y0, Y1;
                if (y0 < 0)        { byc = 0;   Y0 = wy1; Y1 = 0.0f; }
                else if (y0 > 126) { byc = 126; Y0 = 0.0f; Y1 = wy0; }
                else               { byc = y0;  Y0 = wy0; Y1 = wy1; }

                const unsigned ridx = (unsigned)(bxc * XD + byc);
                __half2 hA = __floats2half2_rn(X0 * Y0, X0 * Y1);   // (w00, w01)
                __half2 hB = __floats2half2_rn(X1 * Y0, X1 * Y1);   // (w10, w11)
                uint4 M;
                M.x = *(const unsigned*)&hA;
                M.y = *(const unsigned*)&hB;
                M.z = ridx;
                M.w = 0;
                Ms[m] = M;
            } else {
                Ms[m] = make_uint4(0, 0, 0, 0);
            }
        }
        __syncthreads();

        // Mainloop: 4 steps/trip, stride 16 -> 8 x LDG.128 in flight per warp.
        // One LDG.128 warp-wide = 512 B = the full y-row pair (rows ridx, ridx+1).
        const char* volb = (const char*)g_volh + (lane << 4);
        float S[8];
        #pragma unroll
        for (int i = 0; i < 8; ++i) S[i] = 0.0f;

        for (int m = 4 * w; m < cntPad; m += 16) {
            const uint4 M0 = Ms[m];
            const uint4 M1 = Ms[m + 1];
            const uint4 M2 = Ms[m + 2];
            const uint4 M3 = Ms[m + 3];
            const char* p0 = volb + ((size_t)M0.z << 8);
            const char* p1 = volb + ((size_t)M1.z << 8);
            const char* p2 = volb + ((size_t)M2.z << 8);
            const char* p3 = volb + ((size_t)M3.z << 8);
            const uint4 a0 = __ldg((const uint4*)(p0));
            const uint4 b0 = __ldg((const uint4*)(p0 + 32768));
            const uint4 a1 = __ldg((const uint4*)(p1));
            const uint4 b1 = __ldg((const uint4*)(p1 + 32768));
            const uint4 a2 = __ldg((const uint4*)(p2));
            const uint4 b2 = __ldg((const uint4*)(p2 + 32768));
            const uint4 a3 = __ldg((const uint4*)(p3));
            const uint4 b3 = __ldg((const uint4*)(p3 + 32768));
            pair_acc(S, __byte_perm(M0.x, 0, psel), __byte_perm(M0.y, 0, psel),
                        __byte_perm(M1.x, 0, psel), __byte_perm(M1.y, 0, psel),
                     a0, b0, a1, b1);
            pair_acc(S, __byte_perm(M2.x, 0, psel), __byte_perm(M2.y, 0, psel),
                        __byte_perm(M3.x, 0, psel), __byte_perm(M3.y, 0, psel),
                     a2, b2, a3, b3);
        }

        // Fold y0/y1 half-warp partials (same z in lane and lane+16).
        #pragma unroll
        for (int i = 0; i < 8; ++i)
            S[i] += __shfl_xor_sync(0xffffffffu, S[i], 16);
        if (lane < 16) {
            #pragma unroll
            for (int i = 0; i < 8; ++i)
                Red[w][(lane << 3) + i] = S[i];
        }
        __syncthreads();

        const float acc = Red[0][tid] + Red[1][tid] + Red[2][tid] + Red[3][tid];
        out[((n * XD) + j) * XD + tid] = acc * (float)SCALE_D;
    } else {
        // General path: per-pixel trilinear gather from the ORIGINAL fp32 volume.
        const int z = tid;
        const float kc = (float)z - 63.5f;
        const float bx = fmaf(kc, vx, fmaf(jc, ux, dx)) + 63.5f;
        const float by = fmaf(kc, vy, fmaf(jc, uy, dy)) + 63.5f;
        const float bz = fmaf(kc, vz, fmaf(jc, uz, dz)) + 63.5f;

        float tlo = -3.0e38f, thi = 3.0e38f;
        bool empty = false;
        slab_axis(rx, bx, tlo, thi, empty);
        slab_axis(ry, by, tlo, thi, empty);
        slab_axis(rz, bz, tlo, thi, empty);

        int i0 = 0, i1 = -1;
        if (!empty && thi >= tlo) {
            i0 = max(0, (int)ceilf((tlo - t0) / dt) - 1);
            i1 = min(NDEPTH - 1, (int)floorf((thi - t0) / dt) + 1);
        }

        float sum = 0.0f;
        for (int i = i0; i <= i1; ++i) {
            const float t  = fmaf((float)i, dt, t0);
            const float px = fmaf(t, rx, bx);
            const float py = fmaf(t, ry, by);
            const float pz = fmaf(t, rz, bz);

            const float x0f = floorf(px);
            const float y0f = floorf(py);
            const float z0f = floorf(pz);
            const float fx = px - x0f;
            const float fy = py - y0f;
            const float fz = pz - z0f;
            const int x0 = (int)x0f;
            const int y0 = (int)y0f;
            const int z0 = (int)z0f;

            const int a = x0 * (XD * XD) + y0 * XD + z0;

            const bool xv0 = ((unsigned)x0 < (unsigned)XD);
            const bool xv1 = ((unsigned)(x0 + 1) < (unsigned)XD);
            const bool yv0 = ((unsigned)y0 < (unsigned)XD);
            const bool yv1 = ((unsigned)(y0 + 1) < (unsigned)XD);
            const bool zv0 = ((unsigned)z0 < (unsigned)XD);
            const bool zv1 = ((unsigned)(z0 + 1) < (unsigned)XD);

            const float v000 = (xv0 & yv0 & zv0) ? __ldg(vol + a)                    : 0.0f;
            const float v001 = (xv0 & yv0 & zv1) ? __ldg(vol + a + 1)                : 0.0f;
            const float v010 = (xv0 & yv1 & zv0) ? __ldg(vol + a + XD)               : 0.0f;
            const float v011 = (xv0 & yv1 & zv1) ? __ldg(vol + a + XD + 1)           : 0.0f;
            const float v100 = (xv1 & yv0 & zv0) ? __ldg(vol + a + XD * XD)          : 0.0f;
            const float v101 = (xv1 & yv0 & zv1) ? __ldg(vol + a + XD * XD + 1)      : 0.0f;
            const float v110 = (xv1 & yv1 & zv0) ? __ldg(vol + a + XD * XD + XD)     : 0.0f;
            const float v111 = (xv1 & yv1 & zv1) ? __ldg(vol + a + XD * XD + XD + 1) : 0.0f;

            const float c00 = fmaf(fz, v001 - v000, v000);
            const float c01 = fmaf(fz, v011 - v010, v010);
            const float c10 = fmaf(fz, v101 - v100, v100);
            const float c11 = fmaf(fz, v111 - v110, v110);
            const float c0  = fmaf(fy, c01 - c00, c00);
            const float c1  = fmaf(fy, c11 - c10, c10);
            sum += fmaf(fx, c1 - c0, c0);
        }
        out[((n * XD) + j) * XD + z] = sum * (float)SCALE_D;
    }
}

extern "C" void kernel_launch(void* const* d_in, const int* in_sizes, int n_in,
                              void* d_out, int out_size) {
    const float* vol = (const float*)d_in[0];
    const float* vec = (const float*)d_in[1];
    float* out = (float*)d_out;

    const int N = in_sizes[1] / 12;
    convert_kernel<<<XD * XD * XD / 8 / 256, 256>>>(vol);
    dim3 grid(XD, N);
    dim3 block(128);
    projector_kernel<<<grid, block>>>(vol, vec, out);
}